// round 1
// baseline (speedup 1.0000x reference)
#include <cuda_runtime.h>

#define DM 1024
#define NH 16
#define DH 64
#define BB 2
#define SS 2048
#define MT (BB*SS)

// Scratch (device globals; no allocation allowed in kernel_launch)
__device__ float g_qh[MT*DM];   // [B,H,S,DH]
__device__ float g_kh[MT*DM];
__device__ float g_vh[MT*DM];
__device__ float g_at[MT*DM];   // merged-head attention output [B,S,DM]

// ---------------------------------------------------------------------------
// Tiled SGEMM: out[M,N] = A[M,1024] @ W[1024,N] + bias, optional split-head
// store. BM=128, BN=64, BK=16, 256 threads, 8x4 micro-tile per thread.
// ---------------------------------------------------------------------------
__global__ __launch_bounds__(256) void gemm_k(
    const float* __restrict__ A, const float* __restrict__ W,
    const float* __restrict__ bias, float* __restrict__ out, int split)
{
    __shared__ __align__(16) float As[16][128];   // [k][m]
    __shared__ __align__(16) float Bs[16][64];    // [k][n]

    const int tid = threadIdx.x;
    const int bm = blockIdx.y * 128;
    const int bn = blockIdx.x * 64;
    const int ty = tid >> 4;           // 0..15 (row group of 8)
    const int tx = tid & 15;           // 0..15 (col group of 4)
    const int ar = tid >> 2;           // 0..63
    const int ac = (tid & 3) << 2;     // 0,4,8,12
    const int br = tid >> 4;           // 0..15
    const int bc = (tid & 15) << 2;    // 0..60

    float acc[8][4];
    #pragma unroll
    for (int i = 0; i < 8; i++)
        #pragma unroll
        for (int j = 0; j < 4; j++) acc[i][j] = 0.f;

    for (int k0 = 0; k0 < DM; k0 += 16) {
        #pragma unroll
        for (int p = 0; p < 2; p++) {
            int m = ar + p * 64;
            float4 v = *(const float4*)(A + (size_t)(bm + m) * DM + k0 + ac);
            As[ac + 0][m] = v.x; As[ac + 1][m] = v.y;
            As[ac + 2][m] = v.z; As[ac + 3][m] = v.w;
        }
        *(float4*)&Bs[br][bc] = *(const float4*)(W + (size_t)(k0 + br) * DM + bn + bc);
        __syncthreads();

        #pragma unroll
        for (int kk = 0; kk < 16; kk++) {
            float a[8], bv[4];
            *(float4*)(a)     = *(const float4*)&As[kk][ty * 8];
            *(float4*)(a + 4) = *(const float4*)&As[kk][ty * 8 + 4];
            *(float4*)(bv)    = *(const float4*)&Bs[kk][tx * 4];
            #pragma unroll
            for (int i = 0; i < 8; i++)
                #pragma unroll
                for (int j = 0; j < 4; j++)
                    acc[i][j] = fmaf(a[i], bv[j], acc[i][j]);
        }
        __syncthreads();
    }

    #pragma unroll
    for (int i = 0; i < 8; i++) {
        int m = bm + ty * 8 + i;
        #pragma unroll
        for (int j = 0; j < 4; j++) {
            int n = bn + tx * 4 + j;
            float v = acc[i][j] + bias[n];
            if (split) {
                int b = m >> 11, s = m & (SS - 1);
                int h = n >> 6,  d = n & 63;
                out[(((size_t)(b * NH + h)) * SS + s) * DH + d] = v;
            } else {
                out[(size_t)m * DM + n] = v;
            }
        }
    }
}

// ---------------------------------------------------------------------------
// Flash attention: 64-query tile per block, 64-key inner tiles, depth 64.
// 128 threads: score/PV micro-tile 4x8 per thread, online softmax by
// one-thread-per-row (tid < 64). Writes merged-head layout to g_at.
// ---------------------------------------------------------------------------
__global__ __launch_bounds__(128) void attn_k(const float* __restrict__ mask,
                                              float* __restrict__ outp)
{
    extern __shared__ __align__(16) float sm[];
    float* Qs = sm;                 // [64 d][68] (q-index inner, padded)
    float* Ks = Qs + 64 * 68;       // [64 d][68] (k-index inner, padded)
    float* Vs = Ks + 64 * 68;       // [64 k][64 d]
    float* sc = Vs + 64 * 64;       // [64 q][65]
    float* al = sc + 64 * 65;       // [64] per-row correction factor
    float* ls = al + 64;            // [64] per-row l

    const int tid = threadIdx.x;
    const int q0 = blockIdx.x * 64;
    const int h  = blockIdx.y;
    const int b  = blockIdx.z;
    const float* Qg = g_qh + (size_t)(b * NH + h) * SS * DH;
    const float* Kg = g_kh + (size_t)(b * NH + h) * SS * DH;
    const float* Vg = g_vh + (size_t)(b * NH + h) * SS * DH;

    const int qg = tid & 15;   // 16 groups * 4 query rows
    const int kg = tid >> 4;   //  8 groups * 8 cols

    float acc[4][8];
    #pragma unroll
    for (int i = 0; i < 4; i++)
        #pragma unroll
        for (int j = 0; j < 8; j++) acc[i][j] = 0.f;
    float m_r = -1e30f, l_r = 0.f;

    // Load Q tile, transposed to [d][q]
    for (int idx = tid; idx < 64 * 64; idx += 128) {
        int d = idx & 63, qq = idx >> 6;
        Qs[d * 68 + qq] = Qg[(size_t)(q0 + qq) * DH + d];
    }
    __syncthreads();

    for (int k0 = 0; k0 < SS; k0 += 64) {
        for (int idx = tid; idx < 64 * 64; idx += 128) {
            int d = idx & 63, kk = idx >> 6;
            Ks[d * 68 + kk] = Kg[(size_t)(k0 + kk) * DH + d];
            Vs[kk * 64 + d] = Vg[(size_t)(k0 + kk) * DH + d];
        }
        __syncthreads();

        // Scores: S[4x8] = Q . K^T
        float s[4][8];
        #pragma unroll
        for (int i = 0; i < 4; i++)
            #pragma unroll
            for (int j = 0; j < 8; j++) s[i][j] = 0.f;

        #pragma unroll 8
        for (int d = 0; d < 64; d++) {
            float4 qa  = *(const float4*)&Qs[d * 68 + qg * 4];
            float4 kb0 = *(const float4*)&Ks[d * 68 + kg * 8];
            float4 kb1 = *(const float4*)&Ks[d * 68 + kg * 8 + 4];
            float qv[4]  = {qa.x, qa.y, qa.z, qa.w};
            float kv[8]  = {kb0.x, kb0.y, kb0.z, kb0.w, kb1.x, kb1.y, kb1.z, kb1.w};
            #pragma unroll
            for (int i = 0; i < 4; i++)
                #pragma unroll
                for (int j = 0; j < 8; j++)
                    s[i][j] = fmaf(qv[i], kv[j], s[i][j]);
        }

        // Write scaled + masked logits
        #pragma unroll
        for (int i = 0; i < 4; i++) {
            int qq = q0 + qg * 4 + i;
            #pragma unroll
            for (int j = 0; j < 8; j++) {
                int kk = k0 + kg * 8 + j;
                sc[(qg * 4 + i) * 65 + kg * 8 + j] =
                    s[i][j] * 0.125f - 1e9f * mask[(size_t)qq * SS + kk];
            }
        }
        __syncthreads();

        // Online softmax, one thread per query row
        if (tid < 64) {
            float* row = sc + tid * 65;
            float mx = m_r;
            #pragma unroll 8
            for (int c = 0; c < 64; c++) mx = fmaxf(mx, row[c]);
            float alpha = __expf(m_r - mx);
            float lsum = 0.f;
            #pragma unroll 8
            for (int c = 0; c < 64; c++) {
                float p = __expf(row[c] - mx);
                row[c] = p;
                lsum += p;
            }
            m_r = mx;
            l_r = l_r * alpha + lsum;
            al[tid] = alpha;
        }
        __syncthreads();

        // Rescale accumulators, then O += P @ V
        #pragma unroll
        for (int i = 0; i < 4; i++) {
            float a_i = al[qg * 4 + i];
            #pragma unroll
            for (int j = 0; j < 8; j++) acc[i][j] *= a_i;
        }
        #pragma unroll 8
        for (int kk = 0; kk < 64; kk++) {
            float p[4];
            #pragma unroll
            for (int i = 0; i < 4; i++) p[i] = sc[(qg * 4 + i) * 65 + kk];
            float4 v0 = *(const float4*)&Vs[kk * 64 + kg * 8];
            float4 v1 = *(const float4*)&Vs[kk * 64 + kg * 8 + 4];
            float vv[8] = {v0.x, v0.y, v0.z, v0.w, v1.x, v1.y, v1.z, v1.w};
            #pragma unroll
            for (int i = 0; i < 4; i++)
                #pragma unroll
                for (int j = 0; j < 8; j++)
                    acc[i][j] = fmaf(p[i], vv[j], acc[i][j]);
        }
        __syncthreads();
    }

    if (tid < 64) ls[tid] = l_r;
    __syncthreads();

    #pragma unroll
    for (int i = 0; i < 4; i++) {
        float inv = 1.0f / ls[qg * 4 + i];
        int s_idx = q0 + qg * 4 + i;
        #pragma unroll
        for (int j = 0; j < 8; j++) {
            outp[((size_t)b * SS + s_idx) * DM + h * DH + kg * 8 + j] = acc[i][j] * inv;
        }
    }
}

// ---------------------------------------------------------------------------
extern "C" void kernel_launch(void* const* d_in, const int* in_sizes, int n_in,
                              void* d_out, int out_size)
{
    const float* q    = (const float*)d_in[0];
    const float* k    = (const float*)d_in[1];
    const float* v    = (const float*)d_in[2];
    const float* mask = (const float*)d_in[3];
    const float* wq   = (const float*)d_in[4];
    const float* bq   = (const float*)d_in[5];
    const float* wk   = (const float*)d_in[6];
    const float* bk   = (const float*)d_in[7];
    const float* wv   = (const float*)d_in[8];
    const float* bv   = (const float*)d_in[9];
    const float* wo   = (const float*)d_in[10];
    const float* bo   = (const float*)d_in[11];

    float *qh, *kh, *vh, *at;
    cudaGetSymbolAddress((void**)&qh, g_qh);
    cudaGetSymbolAddress((void**)&kh, g_kh);
    cudaGetSymbolAddress((void**)&vh, g_vh);
    cudaGetSymbolAddress((void**)&at, g_at);

    const int attn_smem = (64*68 + 64*68 + 64*64 + 64*65 + 128) * (int)sizeof(float);
    cudaFuncSetAttribute(attn_k, cudaFuncAttributeMaxDynamicSharedMemorySize, attn_smem);

    dim3 gg(DM / 64, MT / 128);
    gemm_k<<<gg, 256>>>(q, wq, bq, qh, 1);
    gemm_k<<<gg, 256>>>(k, wk, bk, kh, 1);
    gemm_k<<<gg, 256>>>(v, wv, bv, vh, 1);

    dim3 ga(SS / 64, NH, BB);
    attn_k<<<ga, 128, attn_smem>>>(mask, at);

    gemm_k<<<gg, 256>>>(at, wo, bo, (float*)d_out, 0);
}

// round 2
// speedup vs baseline: 1.3807x; 1.3807x over previous
#include <cuda_runtime.h>

#define DM 1024
#define NH 16
#define DH 64
#define BB 2
#define SS 2048
#define MT (BB*SS)

// Scratch (device globals; no allocation allowed in kernel_launch)
__device__ float g_qh[MT*DM];   // [B,H,S,DH]
__device__ float g_kh[MT*DM];
__device__ float g_vh[MT*DM];
__device__ float g_at[MT*DM];   // merged-head attention output [B,S,DM]

// ---------------------------------------------------------------------------
// Helpers
// ---------------------------------------------------------------------------
__device__ __forceinline__ unsigned tf32r(float x) {
    unsigned u;
    asm("cvt.rna.tf32.f32 %0, %1;" : "=r"(u) : "f"(x));
    return u;
}

__device__ __forceinline__ void mma_tf32(float c[4], const unsigned a[4],
                                         const unsigned b[2]) {
    asm volatile(
        "mma.sync.aligned.m16n8k8.row.col.f32.tf32.tf32.f32 "
        "{%0,%1,%2,%3}, {%4,%5,%6,%7}, {%8,%9}, {%0,%1,%2,%3};"
        : "+f"(c[0]), "+f"(c[1]), "+f"(c[2]), "+f"(c[3])
        : "r"(a[0]), "r"(a[1]), "r"(a[2]), "r"(a[3]), "r"(b[0]), "r"(b[1]));
}

// ---------------------------------------------------------------------------
// TF32 tensor-core GEMM: out[M,1024] = A[M,1024] @ W[1024,1024] + bias.
// Block tile 128x128, BK=32, 256 threads (8 warps, warp tile 32x64).
// Operands staged in SMEM directly in mma fragment layout (conflict-free
// LDS.128 / LDS.64 in the hot loop).
// ---------------------------------------------------------------------------
__global__ __launch_bounds__(256) void gemm_tf32(
    const float* __restrict__ A, const float* __restrict__ W,
    const float* __restrict__ bias, float* __restrict__ out, int split)
{
    __shared__ __align__(16) unsigned As[4 * 8 * 128];   // [kt][mt][lane*4+reg]
    __shared__ __align__(16) unsigned Bs[4 * 16 * 64];   // [kt][nt][lane*2+reg]

    const int tid  = threadIdx.x;
    const int lane = tid & 31, wid = tid >> 5;
    const int g = lane >> 2, t = lane & 3;
    const int bm = blockIdx.y * 128, bn = blockIdx.x * 128;
    const int wm = (wid >> 1) * 32, wn = (wid & 1) * 64;
    const int mt0 = wm >> 4;   // first of 2 m16 tiles
    const int nt0 = wn >> 3;   // first of 8 n8 tiles

    float acc[2][8][4];
    #pragma unroll
    for (int i = 0; i < 2; i++)
        #pragma unroll
        for (int j = 0; j < 8; j++)
            #pragma unroll
            for (int r = 0; r < 4; r++) acc[i][j][r] = 0.f;

    for (int k0 = 0; k0 < DM; k0 += 32) {
        // Stage A tile (128x32) into fragment layout
        #pragma unroll
        for (int i = 0; i < 4; i++) {
            int idx = i * 256 + tid;
            int m = idx >> 3, kq = (idx & 7) << 2;
            float4 v = *(const float4*)(A + (size_t)(bm + m) * DM + k0 + kq);
            float vv[4] = {v.x, v.y, v.z, v.w};
            #pragma unroll
            for (int j = 0; j < 4; j++) {
                int k = kq + j;
                int kt = k >> 3, mt = m >> 4, r = m & 15;
                int ln = ((r & 7) << 2) | (k & 3);
                int rg = (r >> 3) | (((k >> 2) & 1) << 1);
                As[((kt * 8 + mt) * 32 + ln) * 4 + rg] = tf32r(vv[j]);
            }
        }
        // Stage W tile (32x128) into fragment layout
        #pragma unroll
        for (int i = 0; i < 4; i++) {
            int idx = i * 256 + tid;
            int kk = idx >> 5, n4 = (idx & 31) << 2;
            float4 v = *(const float4*)(W + (size_t)(k0 + kk) * DM + bn + n4);
            float vv[4] = {v.x, v.y, v.z, v.w};
            #pragma unroll
            for (int j = 0; j < 4; j++) {
                int n = n4 + j;
                int kt = kk >> 3, nt = n >> 3;
                int ln = ((n & 7) << 2) | (kk & 3);
                int rg = (kk >> 2) & 1;
                Bs[((kt * 16 + nt) * 32 + ln) * 2 + rg] = tf32r(vv[j]);
            }
        }
        __syncthreads();

        #pragma unroll
        for (int kt = 0; kt < 4; kt++) {
            unsigned a0[4], a1[4], bf[8][2];
            *(uint4*)a0 = *(const uint4*)&As[((kt * 8 + mt0) * 32 + lane) * 4];
            *(uint4*)a1 = *(const uint4*)&As[((kt * 8 + mt0 + 1) * 32 + lane) * 4];
            #pragma unroll
            for (int j = 0; j < 8; j++)
                *(uint2*)bf[j] = *(const uint2*)&Bs[((kt * 16 + nt0 + j) * 32 + lane) * 2];
            #pragma unroll
            for (int j = 0; j < 8; j++) {
                mma_tf32(acc[0][j], a0, bf[j]);
                mma_tf32(acc[1][j], a1, bf[j]);
            }
        }
        __syncthreads();
    }

    // Epilogue
    #pragma unroll
    for (int i = 0; i < 2; i++) {
        int r0 = bm + wm + i * 16 + g;
        int r1 = r0 + 8;
        #pragma unroll
        for (int j = 0; j < 8; j++) {
            int col = bn + wn + j * 8 + t * 2;
            float b0 = bias[col], b1 = bias[col + 1];
            float v00 = acc[i][j][0] + b0, v01 = acc[i][j][1] + b1;
            float v10 = acc[i][j][2] + b0, v11 = acc[i][j][3] + b1;
            if (split) {
                int h = col >> 6, d = col & 63;
                int b_0 = r0 >> 11, s_0 = r0 & (SS - 1);
                int b_1 = r1 >> 11, s_1 = r1 & (SS - 1);
                float* p0 = out + (((size_t)(b_0 * NH + h)) * SS + s_0) * DH + d;
                float* p1 = out + (((size_t)(b_1 * NH + h)) * SS + s_1) * DH + d;
                p0[0] = v00; p0[1] = v01;
                p1[0] = v10; p1[1] = v11;
            } else {
                float* p0 = out + (size_t)r0 * DM + col;
                float* p1 = out + (size_t)r1 * DM + col;
                p0[0] = v00; p0[1] = v01;
                p1[0] = v10; p1[1] = v11;
            }
        }
    }
}

// ---------------------------------------------------------------------------
// TF32 tensor-core flash attention. Block = (64 q) x (head, batch),
// 128 threads = 4 warps, each warp owns 16 q rows. Key tiles of 64.
// QK^T and PV both via mma.sync; P round-trips through padded smem.
// ---------------------------------------------------------------------------
__global__ __launch_bounds__(128) void attn_tf32(const float* __restrict__ mask,
                                                 float* __restrict__ outp)
{
    extern __shared__ __align__(16) unsigned smu[];
    unsigned* Qf = smu;              // [ktd 8][mt 4][lane*4+reg]  = 4096
    unsigned* Kf = Qf + 4096;        // [ktd 8][ntk 8][lane*2+reg] = 4096
    unsigned* Vf = Kf + 4096;        // [ktk 8][ntd 8][lane*2+reg] = 4096
    unsigned* sc = Vf + 4096;        // [64 q][68]  P matrix (tf32 bits)

    const int tid  = threadIdx.x;
    const int lane = tid & 31, wid = tid >> 5;
    const int g = lane >> 2, t = lane & 3;
    const int q0 = blockIdx.x * 64;
    const int h  = blockIdx.y;
    const int b  = blockIdx.z;
    const float* Qg = g_qh + (size_t)(b * NH + h) * SS * DH;
    const float* Kg = g_kh + (size_t)(b * NH + h) * SS * DH;
    const float* Vg = g_vh + (size_t)(b * NH + h) * SS * DH;

    float o[8][4];
    #pragma unroll
    for (int j = 0; j < 8; j++)
        #pragma unroll
        for (int r = 0; r < 4; r++) o[j][r] = 0.f;
    float m0 = -1e30f, m1 = -1e30f, l0 = 0.f, l1 = 0.f;

    // Stage Q tile (64x64) once, fragment layout
    #pragma unroll
    for (int i = 0; i < 8; i++) {
        int idx = i * 128 + tid;
        int qq = idx >> 4, d4 = (idx & 15) << 2;
        float4 v = *(const float4*)(Qg + (size_t)(q0 + qq) * DH + d4);
        float vv[4] = {v.x, v.y, v.z, v.w};
        #pragma unroll
        for (int j = 0; j < 4; j++) {
            int d = d4 + j;
            int kt = d >> 3, mt = qq >> 4, r = qq & 15;
            int ln = ((r & 7) << 2) | (d & 3);
            int rg = (r >> 3) | (((d >> 2) & 1) << 1);
            Qf[(kt * 4 + mt) * 128 + ln * 4 + rg] = tf32r(vv[j]);
        }
    }
    __syncthreads();

    const int qr0 = q0 + wid * 16 + g;
    const int qr1 = qr0 + 8;

    for (int k0 = 0; k0 < SS; k0 += 64) {
        // Stage K and V tiles (64x64 each), fragment layout
        #pragma unroll
        for (int i = 0; i < 8; i++) {
            int idx = i * 128 + tid;
            int key = idx >> 4, d4 = (idx & 15) << 2;
            float4 kv = *(const float4*)(Kg + (size_t)(k0 + key) * DH + d4);
            float4 vv = *(const float4*)(Vg + (size_t)(k0 + key) * DH + d4);
            float ka[4] = {kv.x, kv.y, kv.z, kv.w};
            float va[4] = {vv.x, vv.y, vv.z, vv.w};
            #pragma unroll
            for (int j = 0; j < 4; j++) {
                int d = d4 + j;
                Kf[((d >> 3) * 8 + (key >> 3)) * 64 +
                   (((key & 7) << 2) | (d & 3)) * 2 + ((d >> 2) & 1)] = tf32r(ka[j]);
                Vf[((key >> 3) * 8 + (d >> 3)) * 64 +
                   (((d & 7) << 2) | (key & 3)) * 2 + ((key >> 2) & 1)] = tf32r(va[j]);
            }
        }
        __syncthreads();

        // Scores: warp's 16 q rows x 64 keys
        float s[8][4];
        #pragma unroll
        for (int j = 0; j < 8; j++)
            #pragma unroll
            for (int r = 0; r < 4; r++) s[j][r] = 0.f;

        #pragma unroll
        for (int ktd = 0; ktd < 8; ktd++) {
            unsigned aq[4];
            *(uint4*)aq = *(const uint4*)&Qf[(ktd * 4 + wid) * 128 + lane * 4];
            #pragma unroll
            for (int nt = 0; nt < 8; nt++) {
                unsigned bk[2];
                *(uint2*)bk = *(const uint2*)&Kf[(ktd * 8 + nt) * 64 + lane * 2];
                mma_tf32(s[nt], aq, bk);
            }
        }

        // Scale + mask
        #pragma unroll
        for (int nt = 0; nt < 8; nt++) {
            int col = k0 + nt * 8 + t * 2;
            float2 mk0 = __ldg((const float2*)(mask + (size_t)qr0 * SS + col));
            float2 mk1 = __ldg((const float2*)(mask + (size_t)qr1 * SS + col));
            s[nt][0] = s[nt][0] * 0.125f - 1e9f * mk0.x;
            s[nt][1] = s[nt][1] * 0.125f - 1e9f * mk0.y;
            s[nt][2] = s[nt][2] * 0.125f - 1e9f * mk1.x;
            s[nt][3] = s[nt][3] * 0.125f - 1e9f * mk1.y;
        }

        // Online softmax (rows g and g+8, stats shared across the 4-lane quad)
        float mx0 = -1e30f, mx1 = -1e30f;
        #pragma unroll
        for (int nt = 0; nt < 8; nt++) {
            mx0 = fmaxf(mx0, fmaxf(s[nt][0], s[nt][1]));
            mx1 = fmaxf(mx1, fmaxf(s[nt][2], s[nt][3]));
        }
        mx0 = fmaxf(mx0, __shfl_xor_sync(0xffffffffu, mx0, 1));
        mx0 = fmaxf(mx0, __shfl_xor_sync(0xffffffffu, mx0, 2));
        mx1 = fmaxf(mx1, __shfl_xor_sync(0xffffffffu, mx1, 1));
        mx1 = fmaxf(mx1, __shfl_xor_sync(0xffffffffu, mx1, 2));

        float nm0 = fmaxf(m0, mx0), nm1 = fmaxf(m1, mx1);
        float al0 = __expf(m0 - nm0), al1 = __expf(m1 - nm1);
        float sum0 = 0.f, sum1 = 0.f;
        int rb0 = (wid * 16 + g) * 68, rb1 = rb0 + 8 * 68;
        #pragma unroll
        for (int nt = 0; nt < 8; nt++) {
            int col = nt * 8 + t * 2;
            float p00 = __expf(s[nt][0] - nm0);
            float p01 = __expf(s[nt][1] - nm0);
            float p10 = __expf(s[nt][2] - nm1);
            float p11 = __expf(s[nt][3] - nm1);
            sum0 += p00 + p01;
            sum1 += p10 + p11;
            sc[rb0 + col]     = tf32r(p00);
            sc[rb0 + col + 1] = tf32r(p01);
            sc[rb1 + col]     = tf32r(p10);
            sc[rb1 + col + 1] = tf32r(p11);
        }
        sum0 += __shfl_xor_sync(0xffffffffu, sum0, 1);
        sum0 += __shfl_xor_sync(0xffffffffu, sum0, 2);
        sum1 += __shfl_xor_sync(0xffffffffu, sum1, 1);
        sum1 += __shfl_xor_sync(0xffffffffu, sum1, 2);
        l0 = l0 * al0 + sum0;
        l1 = l1 * al1 + sum1;
        m0 = nm0; m1 = nm1;

        #pragma unroll
        for (int j = 0; j < 8; j++) {
            o[j][0] *= al0; o[j][1] *= al0;
            o[j][2] *= al1; o[j][3] *= al1;
        }
        __syncwarp();

        // O += P @ V
        int pr0 = (wid * 16 + g) * 68;
        #pragma unroll
        for (int ktk = 0; ktk < 8; ktk++) {
            unsigned ap[4];
            ap[0] = sc[pr0 + ktk * 8 + t];
            ap[1] = sc[pr0 + 8 * 68 + ktk * 8 + t];
            ap[2] = sc[pr0 + ktk * 8 + t + 4];
            ap[3] = sc[pr0 + 8 * 68 + ktk * 8 + t + 4];
            #pragma unroll
            for (int nt = 0; nt < 8; nt++) {
                unsigned bv[2];
                *(uint2*)bv = *(const uint2*)&Vf[(ktk * 8 + nt) * 64 + lane * 2];
                mma_tf32(o[nt], ap, bv);
            }
        }
        __syncthreads();
    }

    // Epilogue: normalize + write merged-head layout
    float inv0 = 1.0f / l0, inv1 = 1.0f / l1;
    #pragma unroll
    for (int nt = 0; nt < 8; nt++) {
        int col = h * DH + nt * 8 + t * 2;
        float2 v0 = make_float2(o[nt][0] * inv0, o[nt][1] * inv0);
        float2 v1 = make_float2(o[nt][2] * inv1, o[nt][3] * inv1);
        *(float2*)(outp + ((size_t)b * SS + qr0) * DM + col) = v0;
        *(float2*)(outp + ((size_t)b * SS + qr1) * DM + col) = v1;
    }
}

// ---------------------------------------------------------------------------
extern "C" void kernel_launch(void* const* d_in, const int* in_sizes, int n_in,
                              void* d_out, int out_size)
{
    const float* q    = (const float*)d_in[0];
    const float* k    = (const float*)d_in[1];
    const float* v    = (const float*)d_in[2];
    const float* mask = (const float*)d_in[3];
    const float* wq   = (const float*)d_in[4];
    const float* bq   = (const float*)d_in[5];
    const float* wk   = (const float*)d_in[6];
    const float* bk   = (const float*)d_in[7];
    const float* wv   = (const float*)d_in[8];
    const float* bv   = (const float*)d_in[9];
    const float* wo   = (const float*)d_in[10];
    const float* bo   = (const float*)d_in[11];

    float *qh, *kh, *vh, *at;
    cudaGetSymbolAddress((void**)&qh, g_qh);
    cudaGetSymbolAddress((void**)&kh, g_kh);
    cudaGetSymbolAddress((void**)&vh, g_vh);
    cudaGetSymbolAddress((void**)&at, g_at);

    const int attn_smem = (4096 * 3 + 64 * 68) * (int)sizeof(unsigned);
    cudaFuncSetAttribute(attn_tf32, cudaFuncAttributeMaxDynamicSharedMemorySize,
                         attn_smem);

    dim3 gg(DM / 128, MT / 128);
    gemm_tf32<<<gg, 256>>>(q, wq, bq, qh, 1);
    gemm_tf32<<<gg, 256>>>(k, wk, bk, kh, 1);
    gemm_tf32<<<gg, 256>>>(v, wv, bv, vh, 1);

    dim3 ga(SS / 64, NH, BB);
    attn_tf32<<<ga, 128, attn_smem>>>(mask, at);

    gemm_tf32<<<gg, 256>>>(at, wo, bo, (float*)d_out, 0);
}